// round 7
// baseline (speedup 1.0000x reference)
#include <cuda_runtime.h>

// AttGCNEncoder: 2x GCNConv(relu) + single-token attention.
// softmax over a length-1 axis == 1  =>  output = relu(gcn2) @ Wv + bv.
// Q/K path is dead code and skipped.
//
// CSC built once per launch (edges grouped by dst), then both GCN
// aggregations are pure gathers (no payload atomics). h is L2-resident.
//
// edge_index dtype is sniffed on-device (int32 vs int64): the harness may
// narrow int64 inputs to int32. Reading int32 data as int64 produced the
// garbage-index atomics that caused cudaErrorInvalidAddressSpace (717).

#define FD 64
#define MAXN 100000
#define MAXE 3200000

__device__ int   g_deg[MAXN];        // in-degree (excluding self loop)
__device__ int   g_rowstart[MAXN];   // CSC row offsets (exclusive scan of deg)
__device__ int   g_cursor[MAXN];     // fill cursors
__device__ float g_dis[MAXN];        // deg^{-1/2} (including self loop)
__device__ int   g_col[MAXE];        // src node per CSC slot
__device__ float g_h[MAXN * FD];     // pre-aggregation linear output
__device__ float g_acc[MAXN * FD];   // post-aggregation activations
__device__ int   g_part[1024];       // block partial sums for the scan
__device__ int   g_is64;             // 1 if edge_index is int64, else int32

// ---------------------------------------------------------------------------
// Dtype sniffer: int64 little-endian values < 2^31 have zero high words.
// Genuine int32 dst indices (random in [0,1e5)) are ~never all zero.
// ---------------------------------------------------------------------------
__global__ void k_sniff(const int* __restrict__ ei32) {
    if (threadIdx.x == 0 && blockIdx.x == 0) {
        int acc = 0;
#pragma unroll
        for (int j = 0; j < 16; j++) acc |= ei32[2 * j + 1];
        g_is64 = (acc == 0) ? 1 : 0;
    }
}

__device__ __forceinline__ void load_edge(const void* ei, int e, int i,
                                          int& src, int& dst) {
    if (g_is64) {
        const long long* p = (const long long*)ei;
        src = (int)p[i];
        dst = (int)p[(long long)e + i];
    } else {
        const int* p = (const int*)ei;
        src = p[i];
        dst = p[e + i];
    }
}

// ---------------------------------------------------------------------------
// CSC construction
// ---------------------------------------------------------------------------

__global__ void k_zero_deg(int n) {
    int i = blockIdx.x * blockDim.x + threadIdx.x;
    if (i < n) g_deg[i] = 0;
}

__global__ void k_count(const void* __restrict__ ei, int e, int n) {
    int i = blockIdx.x * blockDim.x + threadIdx.x;
    if (i < e) {
        int src, dst;
        load_edge(ei, e, i, src, dst);
        if (src >= 0 && src < n && dst >= 0 && dst < n)
            atomicAdd(&g_deg[dst], 1);
    }
}

// Per-block sums of deg
__global__ void k_scan1(int n) {
    __shared__ int s[256];
    int t = threadIdx.x;
    int i = blockIdx.x * 256 + t;
    s[t] = (i < n) ? g_deg[i] : 0;
    __syncthreads();
    for (int off = 128; off > 0; off >>= 1) {
        if (t < off) s[t] += s[t + off];
        __syncthreads();
    }
    if (t == 0) g_part[blockIdx.x] = s[0];
}

// Exclusive scan of block partials (nb <= 1024), single block
__global__ void k_scan2(int nb) {
    __shared__ int s[1024];
    int t = threadIdx.x;
    int v = (t < nb) ? g_part[t] : 0;
    s[t] = v;
    __syncthreads();
    for (int off = 1; off < 1024; off <<= 1) {
        int x = (t >= off) ? s[t - off] : 0;
        __syncthreads();
        s[t] += x;
        __syncthreads();
    }
    if (t < nb) g_part[t] = s[t] - v;   // exclusive
}

// Block-level exclusive scan + global offset; also deg^{-1/2}
__global__ void k_scan3(int n) {
    __shared__ int s[256];
    int t = threadIdx.x;
    int i = blockIdx.x * 256 + t;
    int v = (i < n) ? g_deg[i] : 0;
    s[t] = v;
    __syncthreads();
    for (int off = 1; off < 256; off <<= 1) {
        int x = (t >= off) ? s[t - off] : 0;
        __syncthreads();
        s[t] += x;
        __syncthreads();
    }
    if (i < n) {
        int excl = g_part[blockIdx.x] + s[t] - v;
        g_rowstart[i] = excl;
        g_cursor[i]   = excl;
        g_dis[i] = rsqrtf((float)(v + 1));   // +1 self loop; always > 0
    }
}

__global__ void k_fill(const void* __restrict__ ei, int e, int n) {
    int i = blockIdx.x * blockDim.x + threadIdx.x;
    if (i < e) {
        int src, dst;
        load_edge(ei, e, i, src, dst);
        if (src >= 0 && src < n && dst >= 0 && dst < n) {
            int p = atomicAdd(&g_cursor[dst], 1);
            g_col[p] = src;
        }
    }
}

// ---------------------------------------------------------------------------
// Dense [n,64] @ [64,64] (+ optional bias). Warp-per-row, W staged in SMEM.
// A_ext == nullptr -> read g_acc;  out_ext == nullptr -> write g_h.
// ---------------------------------------------------------------------------

__global__ void k_gemm(const float* __restrict__ A_ext,
                       const float* __restrict__ W,
                       const float* __restrict__ bias,
                       float* __restrict__ out_ext,
                       int n) {
    const float* A   = A_ext   ? A_ext   : (const float*)g_acc;
    float*       out = out_ext ? out_ext : (float*)g_h;

    __shared__ __align__(16) float Ws[FD * FD];
    int t = threadIdx.x;
    {
        const float4* W4 = (const float4*)W;
        float4* Ws4 = (float4*)Ws;
        for (int j = t; j < FD * FD / 4; j += blockDim.x) Ws4[j] = W4[j];
    }
    __syncthreads();

    int lane = t & 31;
    int warp = t >> 5;
    float b0 = 0.f, b1 = 0.f;
    if (bias) { b0 = bias[lane]; b1 = bias[lane + 32]; }

    for (int row = blockIdx.x * 8 + warp; row < n; row += gridDim.x * 8) {
        float a0 = A[row * FD + lane];
        float a1 = A[row * FD + lane + 32];
        float acc0 = 0.f, acc1 = 0.f;
#pragma unroll
        for (int k = 0; k < 32; k++) {
            float ak = __shfl_sync(0xffffffffu, a0, k);
            acc0 = fmaf(ak, Ws[k * FD + lane], acc0);
            acc1 = fmaf(ak, Ws[k * FD + lane + 32], acc1);
        }
#pragma unroll
        for (int k = 0; k < 32; k++) {
            float ak = __shfl_sync(0xffffffffu, a1, k);
            acc0 = fmaf(ak, Ws[(k + 32) * FD + lane], acc0);
            acc1 = fmaf(ak, Ws[(k + 32) * FD + lane + 32], acc1);
        }
        out[row * FD + lane]      = acc0 + b0;
        out[row * FD + lane + 32] = acc1 + b1;
    }
}

// ---------------------------------------------------------------------------
// GCN aggregation (gather form): warp per dst node, lane owns 2 feature cols.
// Reads g_h, writes g_acc.
// out[i] = relu( bias + dis[i]^2*h[i] + sum_{e: dst=i} dis[src]*dis[i]*h[src] )
// ---------------------------------------------------------------------------

__global__ void k_aggr(const float* __restrict__ bias, int n) {
    int gw = (blockIdx.x * blockDim.x + threadIdx.x) >> 5;
    int lane = threadIdx.x & 31;
    if (gw >= n) return;
    int i = gw;

    float di = g_dis[i];
    const float2* h2 = (const float2*)g_h;

    float2 self = h2[i * 32 + lane];
    float w0 = di * di;
    float ax = w0 * self.x;
    float ay = w0 * self.y;

    int start = g_rowstart[i];
    int len   = g_deg[i];
#pragma unroll 4
    for (int j = 0; j < len; j++) {
        int s = __ldg(&g_col[start + j]);
        float w = di * __ldg(&g_dis[s]);
        float2 v = h2[s * 32 + lane];
        ax = fmaf(w, v.x, ax);
        ay = fmaf(w, v.y, ay);
    }

    float bx = bias[2 * lane], by = bias[2 * lane + 1];
    ax = fmaxf(ax + bx, 0.f);
    ay = fmaxf(ay + by, 0.f);
    ((float2*)g_acc)[i * 32 + lane] = make_float2(ax, ay);
}

// ---------------------------------------------------------------------------
// Launch — kernel launches ONLY (graph-capture-safe, no runtime API calls)
// ---------------------------------------------------------------------------

extern "C" void kernel_launch(void* const* d_in, const int* in_sizes, int n_in,
                              void* d_out, int out_size) {
    const float* x  = (const float*)d_in[0];
    const void*  ei = d_in[1];                 // int32 or int64 — sniffed on device
    const float* W1 = (const float*)d_in[2];
    const float* b1 = (const float*)d_in[3];
    const float* W2 = (const float*)d_in[4];
    const float* b2 = (const float*)d_in[5];
    // d_in[6..9] = Wq,bq,Wk,bk : dead (softmax over length-1 axis == 1)
    const float* Wv = (const float*)d_in[10];
    const float* bv = (const float*)d_in[11];

    int n = in_sizes[0] / FD;
    int e = in_sizes[1] / 2;                   // element count / 2 either dtype
    float* outp = (float*)d_out;

    int nb  = (n + 255) / 256;
    int ebl = (e + 255) / 256;

    // CSC build
    k_sniff<<<1, 32>>>((const int*)ei);
    k_zero_deg<<<nb, 256>>>(n);
    k_count<<<ebl, 256>>>(ei, e, n);
    k_scan1<<<nb, 256>>>(n);
    k_scan2<<<1, 1024>>>(nb);
    k_scan3<<<nb, 256>>>(n);
    k_fill<<<ebl, 256>>>(ei, e, n);

    int gemm_blocks = 1184;            // 8 rows/block, row-stride loop
    int aggr_blocks = (n + 7) / 8;     // warp per node, 8 warps/block

    // Layer 1: x @ W1 -> g_h ; aggregate -> g_acc (relu + b1)
    k_gemm<<<gemm_blocks, 256>>>(x, W1, nullptr, nullptr, n);
    k_aggr<<<aggr_blocks, 256>>>(b1, n);
    // Layer 2: g_acc @ W2 -> g_h ; aggregate -> g_acc (relu + b2)
    k_gemm<<<gemm_blocks, 256>>>(nullptr, W2, nullptr, nullptr, n);
    k_aggr<<<aggr_blocks, 256>>>(b2, n);
    // Attention collapses to V projection: g_acc @ Wv + bv -> out
    k_gemm<<<gemm_blocks, 256>>>(nullptr, Wv, bv, outp, n);
}

// round 9
// speedup vs baseline: 1.5297x; 1.5297x over previous
#include <cuda_runtime.h>
#include <cuda_fp16.h>

// AttGCNEncoder: 2x GCNConv(relu) + single-token attention.
// softmax over length-1 axis == 1  =>  output = relu(gcn2) @ Wv + bv.
// Q/K path is dead code and skipped.
//
// R8 changes vs R7 (411us):
//  - GEMM register-blocked 8 rows/warp (was SMEM-BW-bound at 128 LDS/row)
//  - dis[] folded into GEMM epilogue: h' = dis*h stored fp16 -> edge loop is
//    a plain fp16 gather-sum (halves gather bytes, kills per-edge dis loads)
//  - k_count reads only the dst row of edge_index

#define FD 64
#define MAXN 100000
#define MAXE 3200000

__device__ int    g_deg[MAXN];        // in-degree (excluding self loop)
__device__ int    g_rowstart[MAXN];   // CSC row offsets
__device__ int    g_cursor[MAXN];     // fill cursors
__device__ float  g_dis[MAXN];        // deg^{-1/2} (including self loop)
__device__ int    g_col[MAXE];        // src node per CSC slot
__device__ __half g_h16[MAXN * FD];   // dis-scaled linear output (fp16)
__device__ float  g_acc[MAXN * FD];   // post-aggregation activations (fp32)
__device__ int    g_part[1024];       // block partial sums for the scan
__device__ int    g_is64;             // 1 if edge_index is int64, else int32

// ---------------------------------------------------------------------------
// Dtype sniffer: int64 LE values < 2^31 have zero high words.
// ---------------------------------------------------------------------------
__global__ void k_sniff(const int* __restrict__ ei32) {
    if (threadIdx.x == 0 && blockIdx.x == 0) {
        int acc = 0;
#pragma unroll
        for (int j = 0; j < 16; j++) acc |= ei32[2 * j + 1];
        g_is64 = (acc == 0) ? 1 : 0;
    }
}

__device__ __forceinline__ int load_dst(const void* ei, int e, int i) {
    if (g_is64) return (int)((const long long*)ei)[(long long)e + i];
    return ((const int*)ei)[e + i];
}
__device__ __forceinline__ int load_src(const void* ei, int i) {
    if (g_is64) return (int)((const long long*)ei)[i];
    return ((const int*)ei)[i];
}

// ---------------------------------------------------------------------------
// CSC construction
// ---------------------------------------------------------------------------

__global__ void k_zero_deg(int n) {
    int i = blockIdx.x * blockDim.x + threadIdx.x;
    if (i < n) g_deg[i] = 0;
}

__global__ void k_count(const void* __restrict__ ei, int e, int n) {
    int i = blockIdx.x * blockDim.x + threadIdx.x;
    if (i < e) {
        int dst = load_dst(ei, e, i);
        if (dst >= 0 && dst < n) atomicAdd(&g_deg[dst], 1);
    }
}

__global__ void k_scan1(int n) {
    __shared__ int s[256];
    int t = threadIdx.x;
    int i = blockIdx.x * 256 + t;
    s[t] = (i < n) ? g_deg[i] : 0;
    __syncthreads();
    for (int off = 128; off > 0; off >>= 1) {
        if (t < off) s[t] += s[t + off];
        __syncthreads();
    }
    if (t == 0) g_part[blockIdx.x] = s[0];
}

__global__ void k_scan2(int nb) {
    __shared__ int s[1024];
    int t = threadIdx.x;
    int v = (t < nb) ? g_part[t] : 0;
    s[t] = v;
    __syncthreads();
    for (int off = 1; off < 1024; off <<= 1) {
        int x = (t >= off) ? s[t - off] : 0;
        __syncthreads();
        s[t] += x;
        __syncthreads();
    }
    if (t < nb) g_part[t] = s[t] - v;   // exclusive
}

__global__ void k_scan3(int n) {
    __shared__ int s[256];
    int t = threadIdx.x;
    int i = blockIdx.x * 256 + t;
    int v = (i < n) ? g_deg[i] : 0;
    s[t] = v;
    __syncthreads();
    for (int off = 1; off < 256; off <<= 1) {
        int x = (t >= off) ? s[t - off] : 0;
        __syncthreads();
        s[t] += x;
        __syncthreads();
    }
    if (i < n) {
        int excl = g_part[blockIdx.x] + s[t] - v;
        g_rowstart[i] = excl;
        g_cursor[i]   = excl;
        g_dis[i] = rsqrtf((float)(v + 1));   // +1 self loop; always > 0
    }
}

__global__ void k_fill(const void* __restrict__ ei, int e, int n) {
    int i = blockIdx.x * blockDim.x + threadIdx.x;
    if (i < e) {
        int src = load_src(ei, i);
        int dst = load_dst(ei, e, i);
        if (src >= 0 && src < n && dst >= 0 && dst < n) {
            int p = atomicAdd(&g_cursor[dst], 1);
            g_col[p] = src;
        }
    }
}

// ---------------------------------------------------------------------------
// Register-blocked GEMM: [n,64] @ [64,64], 8 rows per warp.
// W staged once in SMEM; each W element read once per 8 rows (8x fewer LDS
// than warp-per-row). Two epilogues:
//   k_gemm_h : out = fp16( dis[row] * (A@W) )      -> g_h16   (layers 1,2)
//   k_gemm_f : out = A@W + bias                    -> fp32 ext (final Wv)
// ---------------------------------------------------------------------------

#define GEMM_BODY(A)                                                        \
    __shared__ __align__(16) float Ws[FD * FD];                             \
    {                                                                       \
        const float4* W4 = (const float4*)W;                                \
        float4* Ws4 = (float4*)Ws;                                          \
        for (int j = threadIdx.x; j < FD * FD / 4; j += blockDim.x)         \
            Ws4[j] = W4[j];                                                 \
    }                                                                       \
    __syncthreads();                                                        \
    int lane = threadIdx.x & 31;                                            \
    int warp = threadIdx.x >> 5;                                            \
    for (int base = (blockIdx.x * 8 + warp) * 8; base < n;                  \
         base += gridDim.x * 64) {                                          \
        float a0[8], a1[8], acc0[8], acc1[8];                               \
        _Pragma("unroll")                                                   \
        for (int j = 0; j < 8; j++) {                                       \
            int r = base + j;                                               \
            a0[j] = (r < n) ? A[r * FD + lane] : 0.f;                       \
            a1[j] = (r < n) ? A[r * FD + lane + 32] : 0.f;                  \
            acc0[j] = 0.f; acc1[j] = 0.f;                                   \
        }                                                                   \
        _Pragma("unroll")                                                   \
        for (int k = 0; k < 32; k++) {                                      \
            float w0 = Ws[k * FD + lane];                                   \
            float w1 = Ws[k * FD + lane + 32];                              \
            _Pragma("unroll")                                               \
            for (int j = 0; j < 8; j++) {                                   \
                float ak = __shfl_sync(0xffffffffu, a0[j], k);              \
                acc0[j] = fmaf(ak, w0, acc0[j]);                            \
                acc1[j] = fmaf(ak, w1, acc1[j]);                            \
            }                                                               \
        }                                                                   \
        _Pragma("unroll")                                                   \
        for (int k = 32; k < 64; k++) {                                     \
            float w0 = Ws[k * FD + lane];                                   \
            float w1 = Ws[k * FD + lane + 32];                              \
            _Pragma("unroll")                                               \
            for (int j = 0; j < 8; j++) {                                   \
                float ak = __shfl_sync(0xffffffffu, a1[j], k - 32);         \
                acc0[j] = fmaf(ak, w0, acc0[j]);                            \
                acc1[j] = fmaf(ak, w1, acc1[j]);                            \
            }                                                               \
        }

__global__ void k_gemm_h(const float* __restrict__ A_ext,
                         const float* __restrict__ W, int n) {
    const float* A = A_ext ? A_ext : (const float*)g_acc;
    GEMM_BODY(A)
        _Pragma("unroll")
        for (int j = 0; j < 8; j++) {
            int r = base + j;
            if (r < n) {
                float d = g_dis[r];
                g_h16[r * FD + lane]      = __float2half_rn(d * acc0[j]);
                g_h16[r * FD + lane + 32] = __float2half_rn(d * acc1[j]);
            }
        }
    }
}

__global__ void k_gemm_f(const float* __restrict__ W,
                         const float* __restrict__ bias,
                         float* __restrict__ out, int n) {
    const float* A = (const float*)g_acc;
    float b0 = bias[threadIdx.x & 31];
    float b1 = bias[(threadIdx.x & 31) + 32];
    GEMM_BODY(A)
        _Pragma("unroll")
        for (int j = 0; j < 8; j++) {
            int r = base + j;
            if (r < n) {
                out[r * FD + lane]      = acc0[j] + b0;
                out[r * FD + lane + 32] = acc1[j] + b1;
            }
        }
    }
}

// ---------------------------------------------------------------------------
// GCN aggregation: warp per dst node, lane owns 2 feature cols (half2 load).
// g_h16 holds h'[s] = dis_s * (xW)[s]   (fp16)
// out[i] = relu( b + dis_i * ( h'[i] + sum_{e: dst=i} h'[src] ) )   (fp32)
// ---------------------------------------------------------------------------

__global__ void k_aggr(const float* __restrict__ bias, int n) {
    int i = (blockIdx.x * blockDim.x + threadIdx.x) >> 5;
    int lane = threadIdx.x & 31;
    if (i >= n) return;

    const __half2* h2 = (const __half2*)g_h16;

    float2 self = __half22float2(h2[i * 32 + lane]);
    float ax = self.x, ay = self.y;

    int start = g_rowstart[i];
    int len   = g_deg[i];
#pragma unroll 8
    for (int j = 0; j < len; j++) {
        int s = __ldg(&g_col[start + j]);
        float2 v = __half22float2(__ldg(&h2[s * 32 + lane]));
        ax += v.x;
        ay += v.y;
    }

    float di = g_dis[i];
    float bx = bias[2 * lane], by = bias[2 * lane + 1];
    ax = fmaxf(fmaf(di, ax, bx), 0.f);
    ay = fmaxf(fmaf(di, ay, by), 0.f);
    ((float2*)g_acc)[i * 32 + lane] = make_float2(ax, ay);
}

// ---------------------------------------------------------------------------
// Launch — kernel launches ONLY (graph-capture-safe, no runtime API calls)
// ---------------------------------------------------------------------------

extern "C" void kernel_launch(void* const* d_in, const int* in_sizes, int n_in,
                              void* d_out, int out_size) {
    const float* x  = (const float*)d_in[0];
    const void*  ei = d_in[1];                 // int32 or int64 — sniffed on device
    const float* W1 = (const float*)d_in[2];
    const float* b1 = (const float*)d_in[3];
    const float* W2 = (const float*)d_in[4];
    const float* b2 = (const float*)d_in[5];
    // d_in[6..9] = Wq,bq,Wk,bk : dead (softmax over length-1 axis == 1)
    const float* Wv = (const float*)d_in[10];
    const float* bv = (const float*)d_in[11];

    int n = in_sizes[0] / FD;
    int e = in_sizes[1] / 2;
    float* outp = (float*)d_out;

    int nb  = (n + 255) / 256;
    int ebl = (e + 255) / 256;

    // CSC build
    k_sniff<<<1, 32>>>((const int*)ei);
    k_zero_deg<<<nb, 256>>>(n);
    k_count<<<ebl, 256>>>(ei, e, n);
    k_scan1<<<nb, 256>>>(n);
    k_scan2<<<1, 1024>>>(nb);
    k_scan3<<<nb, 256>>>(n);
    k_fill<<<ebl, 256>>>(ei, e, n);

    // 8 warps/block, 8 rows/warp -> 64 rows/block
    int gemm_blocks = (n + 63) / 64;
    int aggr_blocks = (n + 7) / 8;     // warp per node, 8 warps/block

    // Layer 1: g_h16 = fp16(dis * (x@W1)) ; aggregate -> g_acc (relu, +b1)
    k_gemm_h<<<gemm_blocks, 256>>>(x, W1, n);
    k_aggr<<<aggr_blocks, 256>>>(b1, n);
    // Layer 2
    k_gemm_h<<<gemm_blocks, 256>>>(nullptr, W2, n);
    k_aggr<<<aggr_blocks, 256>>>(b2, n);
    // Attention collapses to V projection: g_acc @ Wv + bv -> out
    k_gemm_f<<<gemm_blocks, 256>>>(Wv, bv, outp, n);
}

// round 10
// speedup vs baseline: 1.6303x; 1.0658x over previous
#include <cuda_runtime.h>
#include <cuda_fp16.h>

// AttGCNEncoder: 2x GCNConv(relu) + single-token attention.
// softmax over length-1 axis == 1  =>  output = relu(gcn2) @ Wv + bv.
// Q/K path is dead code and skipped.
//
// R10 vs R9 (269us):
//  - GEMM rewritten around fma.rn.f32x2 (packed dual-FMA, fp32 precision):
//    even/odd-k pair accumulation, A tile staged in SMEM (broadcast LDS.64
//    replaces shfl+pack), W staged k-pair-transposed. ~2x fewer fma-pipe ops.
//  - sniff merged into zero_deg (one fewer launch; ncu -s5 now lands on gemm).

#define FD 64
#define MAXN 100000
#define MAXE 3200000

__device__ int    g_deg[MAXN];        // in-degree (excluding self loop)
__device__ int    g_rowstart[MAXN];   // CSC row offsets
__device__ int    g_cursor[MAXN];     // fill cursors
__device__ float  g_dis[MAXN];        // deg^{-1/2} (including self loop)
__device__ int    g_col[MAXE];        // src node per CSC slot
__device__ __half g_h16[MAXN * FD];   // dis-scaled linear output (fp16)
__device__ float  g_acc[MAXN * FD];   // post-aggregation activations (fp32)
__device__ int    g_part[1024];       // block partial sums for the scan
__device__ int    g_is64;             // 1 if edge_index is int64, else int32

typedef unsigned long long u64;

// packed f32x2 fma: acc = a*b + acc (elementwise on 2-wide packs)
__device__ __forceinline__ void fma2(u64& acc, u64 a, u64 b) {
    asm("fma.rn.f32x2 %0, %1, %2, %0;" : "+l"(acc) : "l"(a), "l"(b));
}
__device__ __forceinline__ float hsum2(u64 v) {
    float lo, hi;
    asm("mov.b64 {%0,%1}, %2;" : "=f"(lo), "=f"(hi) : "l"(v));
    return lo + hi;
}

// ---------------------------------------------------------------------------
// zero deg + dtype sniff (int64 LE values < 2^31 have zero high words)
// ---------------------------------------------------------------------------
__global__ void k_zero_sniff(const int* __restrict__ ei32, int n) {
    int i = blockIdx.x * blockDim.x + threadIdx.x;
    if (i < n) g_deg[i] = 0;
    if (i == 0) {
        int acc = 0;
#pragma unroll
        for (int j = 0; j < 16; j++) acc |= ei32[2 * j + 1];
        g_is64 = (acc == 0) ? 1 : 0;
    }
}

__device__ __forceinline__ int load_dst(const void* ei, int e, int i) {
    if (g_is64) return (int)((const long long*)ei)[(long long)e + i];
    return ((const int*)ei)[e + i];
}
__device__ __forceinline__ int load_src(const void* ei, int i) {
    if (g_is64) return (int)((const long long*)ei)[i];
    return ((const int*)ei)[i];
}

// ---------------------------------------------------------------------------
// CSC construction
// ---------------------------------------------------------------------------

__global__ void k_count(const void* __restrict__ ei, int e, int n) {
    int i = blockIdx.x * blockDim.x + threadIdx.x;
    if (i < e) {
        int dst = load_dst(ei, e, i);
        if (dst >= 0 && dst < n) atomicAdd(&g_deg[dst], 1);
    }
}

__global__ void k_scan1(int n) {
    __shared__ int s[256];
    int t = threadIdx.x;
    int i = blockIdx.x * 256 + t;
    s[t] = (i < n) ? g_deg[i] : 0;
    __syncthreads();
    for (int off = 128; off > 0; off >>= 1) {
        if (t < off) s[t] += s[t + off];
        __syncthreads();
    }
    if (t == 0) g_part[blockIdx.x] = s[0];
}

__global__ void k_scan2(int nb) {
    __shared__ int s[1024];
    int t = threadIdx.x;
    int v = (t < nb) ? g_part[t] : 0;
    s[t] = v;
    __syncthreads();
    for (int off = 1; off < 1024; off <<= 1) {
        int x = (t >= off) ? s[t - off] : 0;
        __syncthreads();
        s[t] += x;
        __syncthreads();
    }
    if (t < nb) g_part[t] = s[t] - v;   // exclusive
}

__global__ void k_scan3(int n) {
    __shared__ int s[256];
    int t = threadIdx.x;
    int i = blockIdx.x * 256 + t;
    int v = (i < n) ? g_deg[i] : 0;
    s[t] = v;
    __syncthreads();
    for (int off = 1; off < 256; off <<= 1) {
        int x = (t >= off) ? s[t - off] : 0;
        __syncthreads();
        s[t] += x;
        __syncthreads();
    }
    if (i < n) {
        int excl = g_part[blockIdx.x] + s[t] - v;
        g_rowstart[i] = excl;
        g_cursor[i]   = excl;
        g_dis[i] = rsqrtf((float)(v + 1));   // +1 self loop; always > 0
    }
}

__global__ void k_fill(const void* __restrict__ ei, int e, int n) {
    int i = blockIdx.x * blockDim.x + threadIdx.x;
    if (i < e) {
        int src = load_src(ei, i);
        int dst = load_dst(ei, e, i);
        if (src >= 0 && src < n && dst >= 0 && dst < n) {
            int p = atomicAdd(&g_cursor[dst], 1);
            g_col[p] = src;
        }
    }
}

// ---------------------------------------------------------------------------
// GEMM [n,64]@[64,64] with packed f32x2 FMA, even/odd-k pair accumulation.
// One 64-row tile per block; A tile + k-pair-transposed W staged in SMEM.
// Thread (warp w, lane l): rows w*8..w*8+7, output cols l and l+32.
//   acc0p[j] = packed (sum over even k, sum over odd k) for col l
// mode 0: out = fp16( dis[row] * (A@W) ) -> g_h16
// mode 1: out = A@W + bias              -> outf
// ---------------------------------------------------------------------------

__global__ __launch_bounds__(256) void k_gemm(const float* __restrict__ A_ext,
                                              const float* __restrict__ W,
                                              const float* __restrict__ bias,
                                              float* __restrict__ outf,
                                              int n, int mode) {
    const float* A = A_ext ? A_ext : (const float*)g_acc;

    __shared__ __align__(16) float2 Wp[32 * FD];  // [t][c] = (W[2t][c], W[2t+1][c])
    __shared__ __align__(16) float  As[FD * FD];  // 64 rows x 64 cols

    int tid = threadIdx.x;
    // Stage W transposed into k-pairs
    for (int idx = tid; idx < 32 * FD; idx += 256) {
        int t = idx >> 6, c = idx & 63;
        Wp[idx] = make_float2(W[(2 * t) * FD + c], W[(2 * t + 1) * FD + c]);
    }
    // Stage A tile (guarded)
    int rowbase = blockIdx.x * FD;
    {
        const float4* A4 = (const float4*)(A + (size_t)rowbase * FD);
        float4* As4 = (float4*)As;
        int lim = (n - rowbase) * (FD / 4);          // valid float4 count
        for (int idx = tid; idx < FD * FD / 4; idx += 256)
            As4[idx] = (idx < lim) ? A4[idx] : make_float4(0.f, 0.f, 0.f, 0.f);
    }
    __syncthreads();

    int lane = tid & 31;
    int warp = tid >> 5;

    u64 acc0p[8], acc1p[8];
#pragma unroll
    for (int j = 0; j < 8; j++) { acc0p[j] = 0ull; acc1p[j] = 0ull; }

    const u64* As2 = (const u64*)As;   // [row][t] = packed (A[row][2t], A[row][2t+1])
    const u64* Wp2 = (const u64*)Wp;

#pragma unroll
    for (int t = 0; t < 32; t++) {
        u64 w0 = Wp2[t * FD + lane];
        u64 w1 = Wp2[t * FD + lane + 32];
#pragma unroll
        for (int j = 0; j < 8; j++) {
            u64 aa = As2[(warp * 8 + j) * 32 + t];   // broadcast LDS.64
            fma2(acc0p[j], aa, w0);
            fma2(acc1p[j], aa, w1);
        }
    }

    if (mode == 0) {
#pragma unroll
        for (int j = 0; j < 8; j++) {
            int r = rowbase + warp * 8 + j;
            if (r < n) {
                float d = g_dis[r];
                g_h16[r * FD + lane]      = __float2half_rn(d * hsum2(acc0p[j]));
                g_h16[r * FD + lane + 32] = __float2half_rn(d * hsum2(acc1p[j]));
            }
        }
    } else {
        float b0 = bias[lane], b1 = bias[lane + 32];
#pragma unroll
        for (int j = 0; j < 8; j++) {
            int r = rowbase + warp * 8 + j;
            if (r < n) {
                outf[r * FD + lane]      = hsum2(acc0p[j]) + b0;
                outf[r * FD + lane + 32] = hsum2(acc1p[j]) + b1;
            }
        }
    }
}

// ---------------------------------------------------------------------------
// GCN aggregation: warp per dst node, lane owns 2 feature cols (half2 load).
// g_h16 holds h'[s] = dis_s * (xW)[s]   (fp16)
// out[i] = relu( b + dis_i * ( h'[i] + sum_{e: dst=i} h'[src] ) )   (fp32)
// ---------------------------------------------------------------------------

__global__ void k_aggr(const float* __restrict__ bias, int n) {
    int i = (blockIdx.x * blockDim.x + threadIdx.x) >> 5;
    int lane = threadIdx.x & 31;
    if (i >= n) return;

    const __half2* h2 = (const __half2*)g_h16;

    float2 self = __half22float2(h2[i * 32 + lane]);
    float ax = self.x, ay = self.y;

    int start = g_rowstart[i];
    int len   = g_deg[i];
#pragma unroll 8
    for (int j = 0; j < len; j++) {
        int s = __ldg(&g_col[start + j]);
        float2 v = __half22float2(__ldg(&h2[s * 32 + lane]));
        ax += v.x;
        ay += v.y;
    }

    float di = g_dis[i];
    float bx = bias[2 * lane], by = bias[2 * lane + 1];
    ax = fmaxf(fmaf(di, ax, bx), 0.f);
    ay = fmaxf(fmaf(di, ay, by), 0.f);
    ((float2*)g_acc)[i * 32 + lane] = make_float2(ax, ay);
}

// ---------------------------------------------------------------------------
// Launch — kernel launches ONLY (graph-capture-safe, no runtime API calls)
// Order puts gemm1 at launch index 5 so ncu (-s 5 -c 1) profiles it.
// ---------------------------------------------------------------------------

extern "C" void kernel_launch(void* const* d_in, const int* in_sizes, int n_in,
                              void* d_out, int out_size) {
    const float* x  = (const float*)d_in[0];
    const void*  ei = d_in[1];                 // int32 or int64 — sniffed on device
    const float* W1 = (const float*)d_in[2];
    const float* b1 = (const float*)d_in[3];
    const float* W2 = (const float*)d_in[4];
    const float* b2 = (const float*)d_in[5];
    // d_in[6..9] = Wq,bq,Wk,bk : dead (softmax over length-1 axis == 1)
    const float* Wv = (const float*)d_in[10];
    const float* bv = (const float*)d_in[11];

    int n = in_sizes[0] / FD;
    int e = in_sizes[1] / 2;
    float* outp = (float*)d_out;

    int nb  = (n + 255) / 256;
    int ebl = (e + 255) / 256;
    int gemm_blocks = (n + 63) / 64;
    int aggr_blocks = (n + 7) / 8;     // warp per node, 8 warps/block

    // 0-4: CSC prefix (deg, dis, rowstart)
    k_zero_sniff<<<nb, 256>>>((const int*)ei, n);      // 0
    k_count<<<ebl, 256>>>(ei, e, n);                   // 1
    k_scan1<<<nb, 256>>>(n);                           // 2
    k_scan2<<<1, 1024>>>(nb);                          // 3
    k_scan3<<<nb, 256>>>(n);                           // 4
    // 5: layer-1 linear (profiled by ncu -s 5 -c 1)
    k_gemm<<<gemm_blocks, 256>>>(x, W1, nullptr, nullptr, n, 0);   // 5
    // 6: CSC adjacency fill (independent of gemm1; must precede aggr1)
    k_fill<<<ebl, 256>>>(ei, e, n);                    // 6
    // Layer 1 aggregate
    k_aggr<<<aggr_blocks, 256>>>(b1, n);               // 7
    // Layer 2
    k_gemm<<<gemm_blocks, 256>>>(nullptr, W2, nullptr, nullptr, n, 0);  // 8
    k_aggr<<<aggr_blocks, 256>>>(b2, n);               // 9
    // Attention collapses to V projection
    k_gemm<<<gemm_blocks, 256>>>(nullptr, Wv, bv, outp, n, 1);          // 10
}